// round 3
// baseline (speedup 1.0000x reference)
#include <cuda_runtime.h>
#include <cstdint>

#define S_TOK 8192
#define D_DIM 2048
#define E_EXP 64
#define CAP   128

// ---------------- scratch ----------------
__device__ int   g_idx[S_TOK];
__device__ float g_gate1[S_TOK];
__device__ int   g_loc[S_TOK];
__device__ float g_partialGateSum[128 * E_EXP];   // per-gemm-block softmax sums
__device__ float g_laux;                          // aux loss scratch (committed post-join)

// ---------------- GEMM + fused softmax/argmax epilogue ----------------
// 128 blocks x 256 threads. 64-token x 64-expert tile, 4x4 thread tile.
#define GEMM_BLOCKS 128
#define BM 64
#define BN 64
#define BK 32
#define SROW 68   // padded row stride

__global__ void __launch_bounds__(256) gemm_kernel(const float* __restrict__ x,
                                                   const float* __restrict__ wg) {
    __shared__ float sm[2 * BK * SROW];       // Xs[32][68] | Ws[32][68]; reused as Ls[64][68]
    __shared__ float pg[8 * E_EXP];
    float (*Xs)[SROW] = (float(*)[SROW])sm;
    float (*Ws)[SROW] = (float(*)[SROW])(sm + BK * SROW);
    float (*Ls)[SROW] = (float(*)[SROW])sm;

    const int tid = threadIdx.x;
    const int m0  = blockIdx.x * BM;
    const int tx  = tid & 15;    // expert group: tx*4..tx*4+3
    const int ty  = tid >> 4;    // token  group: ty*4..ty*4+3

    int rowi[2], c4i[2];
#pragma unroll
    for (int i = 0; i < 2; i++) {
        int f = tid + i * 256;   // 512 float4 per 64x32 tile
        rowi[i] = f >> 3;
        c4i[i]  = f & 7;
    }

    float4 xr[2], wr[2];
#pragma unroll
    for (int i = 0; i < 2; i++) {
        xr[i] = *(const float4*)(x  + (size_t)(m0 + rowi[i]) * D_DIM + c4i[i] * 4);
        wr[i] = *(const float4*)(wg + (size_t)rowi[i] * D_DIM + c4i[i] * 4);
    }

    float acc[4][4];
#pragma unroll
    for (int i = 0; i < 4; i++)
#pragma unroll
        for (int j = 0; j < 4; j++) acc[i][j] = 0.0f;

    const int NT = D_DIM / BK;
    for (int kt = 0; kt < NT; kt++) {
#pragma unroll
        for (int i = 0; i < 2; i++) {
            int c = c4i[i] * 4, r = rowi[i];
            Xs[c + 0][r] = xr[i].x; Xs[c + 1][r] = xr[i].y;
            Xs[c + 2][r] = xr[i].z; Xs[c + 3][r] = xr[i].w;
            Ws[c + 0][r] = wr[i].x; Ws[c + 1][r] = wr[i].y;
            Ws[c + 2][r] = wr[i].z; Ws[c + 3][r] = wr[i].w;
        }
        __syncthreads();

        if (kt + 1 < NT) {
            int k0 = (kt + 1) * BK;
#pragma unroll
            for (int i = 0; i < 2; i++) {
                xr[i] = *(const float4*)(x  + (size_t)(m0 + rowi[i]) * D_DIM + k0 + c4i[i] * 4);
                wr[i] = *(const float4*)(wg + (size_t)rowi[i] * D_DIM + k0 + c4i[i] * 4);
            }
        }

#pragma unroll
        for (int k = 0; k < BK; k++) {
            float4 a4 = *(const float4*)&Xs[k][ty * 4];
            float4 b4 = *(const float4*)&Ws[k][tx * 4];
            float a[4] = {a4.x, a4.y, a4.z, a4.w};
            float b[4] = {b4.x, b4.y, b4.z, b4.w};
#pragma unroll
            for (int i = 0; i < 4; i++)
#pragma unroll
                for (int j = 0; j < 4; j++) acc[i][j] = fmaf(a[i], b[j], acc[i][j]);
        }
        __syncthreads();
    }

    // ---------- softmax epilogue ----------
#pragma unroll
    for (int i = 0; i < 4; i++)
        *(float4*)&Ls[ty * 4 + i][tx * 4] = make_float4(acc[i][0], acc[i][1], acc[i][2], acc[i][3]);
    __syncthreads();

    const int wpid = tid >> 5, lane = tid & 31;
    float pa0 = 0.0f, pa1 = 0.0f;
#pragma unroll
    for (int t = 0; t < 8; t++) {
        const int row = wpid * 8 + t;
        float l0 = Ls[row][lane];
        float l1 = Ls[row][lane + 32];
        float mv; int mi;                     // argmax, first-occurrence tie-break
        if (l0 >= l1) { mv = l0; mi = lane; } else { mv = l1; mi = lane + 32; }
#pragma unroll
        for (int off = 16; off; off >>= 1) {
            float ov = __shfl_down_sync(0xffffffffu, mv, off);
            int   oi = __shfl_down_sync(0xffffffffu, mi, off);
            if (ov > mv || (ov == mv && oi < mi)) { mv = ov; mi = oi; }
        }
        mv = __shfl_sync(0xffffffffu, mv, 0);
        mi = __shfl_sync(0xffffffffu, mi, 0);

        float e0 = expf(l0 - mv), e1 = expf(l1 - mv);
        float sum = e0 + e1;
#pragma unroll
        for (int off = 16; off; off >>= 1) sum += __shfl_down_sync(0xffffffffu, sum, off);
        sum = __shfl_sync(0xffffffffu, sum, 0);
        float inv = 1.0f / sum;

        pa0 += e0 * inv;
        pa1 += e1 * inv;
        if (lane == 0) { g_idx[m0 + row] = mi; g_gate1[m0 + row] = inv; }
    }
    pg[wpid * E_EXP + lane]      = pa0;
    pg[wpid * E_EXP + lane + 32] = pa1;
    __syncthreads();
    if (tid < E_EXP) {
        float s = 0.0f;
#pragma unroll
        for (int w8 = 0; w8 < 8; w8++) s += pg[w8 * E_EXP + tid];
        g_partialGateSum[(size_t)blockIdx.x * E_EXP + tid] = s;
    }
}

// ---------------- ordered per-expert rank + aux loss (single block) ----------------
__global__ void __launch_bounds__(1024) scan_aux_kernel() {
    __shared__ int   hist[32 * E_EXP];
    __shared__ float red[16 * E_EXP];
    __shared__ int   cntS[E_EXP];
    __shared__ float vals[E_EXP];

    const int tid = threadIdx.x, lane = tid & 31, w = tid >> 5;
    hist[tid] = 0; hist[tid + 1024] = 0;
    __syncthreads();

    int eArr[8], locArr[8];
    const int base = w * 256;
#pragma unroll
    for (int g = 0; g < 8; g++) {
        const int s = base + g * 32 + lane;
        const int e = g_idx[s];
        unsigned mask = __match_any_sync(0xffffffffu, e);
        int rank = __popc(mask & ((1u << lane) - 1u));
        int bcnt = hist[w * E_EXP + e];
        eArr[g] = e; locArr[g] = bcnt + rank;
        __syncwarp();
        if (lane == __ffs(mask) - 1) hist[w * E_EXP + e] = bcnt + __popc(mask);
        __syncwarp();
    }
    __syncthreads();

    if (tid < E_EXP) {
        int running = 0;
        for (int ww = 0; ww < 32; ww++) {
            int c = hist[ww * E_EXP + tid];
            hist[ww * E_EXP + tid] = running;
            running += c;
        }
        cntS[tid] = running;
    }
    __syncthreads();

#pragma unroll
    for (int g = 0; g < 8; g++)
        g_loc[base + g * 32 + lane] = hist[w * E_EXP + eArr[g]] + locArr[g];

    {
        const int e = tid & 63, r = tid >> 6;  // 16 slices x 64 experts
        float sum = 0.0f;
        for (int p = r * 8; p < r * 8 + 8; p++) sum += g_partialGateSum[(size_t)p * E_EXP + e];
        red[(size_t)r * E_EXP + e] = sum;
    }
    __syncthreads();
    if (tid < E_EXP) {
        float me = 0.0f;
#pragma unroll
        for (int r = 0; r < 16; r++) me += red[r * E_EXP + tid];
        me /= (float)S_TOK;
        float ce = (float)cntS[tid] / (float)S_TOK;
        vals[tid] = me * ce;
    }
    __syncthreads();
    if (tid == 0) {
        float a = 0.0f;
        for (int e = 0; e < E_EXP; e++) a += vals[e];
        g_laux = a * (float)E_EXP;   // mean * E*E == sum * E
    }
}

// ---------------- scatter combine + mask + l_aux commit (post-join) ----------------
__global__ void scatter_kernel(float* __restrict__ combine, float* __restrict__ maskp,
                               float* __restrict__ lauxp) {
    const int s = blockIdx.x * blockDim.x + threadIdx.x;
    if (s == 0 && lauxp) *lauxp = g_laux;
    if (s >= S_TOK) return;
    const int loc = g_loc[s];
    if (loc >= CAP) return;   // dropped: row stays zero
    const int e = g_idx[s];
    const size_t off = (size_t)s * (E_EXP * CAP) + (size_t)e * CAP + loc;
    combine[off] = g_gate1[s];
    if (maskp) maskp[off] = 1.0f;
}

// ---------------- stream/event handles for graph fork (static init, no device mem alloc) ----------------
namespace {
cudaStream_t g_s2     = nullptr;
cudaEvent_t  g_evFork = nullptr;
cudaEvent_t  g_evJoin = nullptr;
struct ForkInit {
    ForkInit() {
        if (cudaStreamCreateWithFlags(&g_s2, cudaStreamNonBlocking) != cudaSuccess) g_s2 = nullptr;
        if (cudaEventCreateWithFlags(&g_evFork, cudaEventDisableTiming) != cudaSuccess) g_evFork = nullptr;
        if (cudaEventCreateWithFlags(&g_evJoin, cudaEventDisableTiming) != cudaSuccess) g_evJoin = nullptr;
    }
};
ForkInit g_forkInit;
}

// ---------------- launch ----------------
extern "C" void kernel_launch(void* const* d_in, const int* in_sizes, int n_in,
                              void* d_out, int out_size) {
    const float* x  = (const float*)d_in[0];   // [S, D]
    const float* wg = (const float*)d_in[1];   // [E, D]
    float* out = (float*)d_out;

    const long long SEC = (long long)S_TOK * E_EXP * CAP;  // 67,108,864
    float* lauxp   = nullptr;
    float* combine = out;
    float* maskp   = nullptr;
    if ((long long)out_size >= 1 + 2 * SEC) {          // [l_aux, combine, mask]
        lauxp = out; combine = out + 1; maskp = out + 1 + SEC;
    } else if ((long long)out_size == 1 + SEC) {       // [l_aux, combine]
        lauxp = out; combine = out + 1;
    }

    const bool forked = (g_s2 != nullptr) && (g_evFork != nullptr) && (g_evJoin != nullptr);

    if (forked) {
        // fork: zero-fill runs as an independent graph branch, concurrent with compute
        cudaEventRecord(g_evFork, 0);
        cudaStreamWaitEvent(g_s2, g_evFork, 0);
        cudaMemsetAsync(d_out, 0, (size_t)out_size * sizeof(float), g_s2);
        cudaEventRecord(g_evJoin, g_s2);
    } else {
        cudaMemsetAsync(d_out, 0, (size_t)out_size * sizeof(float), 0);
    }

    gemm_kernel<<<GEMM_BLOCKS, 256>>>(x, wg);
    scan_aux_kernel<<<1, 1024>>>();

    if (forked) cudaStreamWaitEvent(0, g_evJoin, 0);   // join before touching out
    scatter_kernel<<<(S_TOK + 255) / 256, 256>>>(combine, maskp, lauxp);
}

// round 4
// speedup vs baseline: 1.8827x; 1.8827x over previous
#include <cuda_runtime.h>
#include <cstdint>

#define S_TOK 8192
#define D_DIM 2048
#define E_EXP 64
#define CAP   128

// ---------------- scratch ----------------
__device__ int   g_idx[S_TOK];
__device__ float g_gate1[S_TOK];
__device__ float g_partialGateSum[128 * E_EXP];   // per-gemm-block softmax sums

// ---------------- packed fp32x2 helpers (Blackwell FFMA2) ----------------
__device__ __forceinline__ uint64_t pack2(float lo, float hi) {
    uint64_t p;
    asm("mov.b64 %0, {%1, %2};" : "=l"(p) : "f"(lo), "f"(hi));
    return p;
}
__device__ __forceinline__ void unpack2(uint64_t p, float& lo, float& hi) {
    asm("mov.b64 {%0, %1}, %2;" : "=f"(lo), "=f"(hi) : "l"(p));
}
#define FMA2(d, a, b) asm("fma.rn.f32x2 %0, %1, %2, %0;" : "+l"(d) : "l"(a), "l"(b))

// ---------------- fused GEMM+softmax + output zeroing ----------------
// Blocks 0..127   : 64-token x 64-expert GEMM tile (256 thr, 4x4 thread tile, FFMA2)
// Blocks 128..1919: zero-fill d_out (concurrent, soaks idle DRAM + issue slots)
#define GEMM_BLOCKS 128
#define ZERO_BLOCKS 1792
#define BM 64
#define BN 64
#define BK 32
#define SROW 68   // padded row stride

__global__ void __launch_bounds__(256) fused_kernel(const float* __restrict__ x,
                                                    const float* __restrict__ wg,
                                                    float* __restrict__ out,
                                                    long long out_elems) {
    // ---------- zero role ----------
    if (blockIdx.x >= GEMM_BLOCKS) {
        const long long zb = blockIdx.x - GEMM_BLOCKS;
        const long long total4 = out_elems >> 2;
        float4* o4 = (float4*)out;
        const float4 z = make_float4(0.f, 0.f, 0.f, 0.f);
        const long long stride = (long long)ZERO_BLOCKS * 256;
        for (long long i = zb * 256 + threadIdx.x; i < total4; i += stride) o4[i] = z;
        if (zb == 0 && threadIdx.x == 0)
            for (long long i = total4 * 4; i < out_elems; i++) out[i] = 0.f;
        return;
    }

    // ---------- GEMM role ----------
    __shared__ float sm[2 * BK * SROW];       // Xs[32][68] | Ws[32][68]; reused as Ls[64][68]
    __shared__ float pg[8 * E_EXP];
    float (*Xs)[SROW] = (float(*)[SROW])sm;
    float (*Ws)[SROW] = (float(*)[SROW])(sm + BK * SROW);
    float (*Ls)[SROW] = (float(*)[SROW])sm;

    const int tid = threadIdx.x;
    const int m0  = blockIdx.x * BM;
    const int tx  = tid & 15;    // expert group: tx*4..tx*4+3
    const int ty  = tid >> 4;    // token  group: ty*4..ty*4+3

    int rowi[2], c4i[2];
#pragma unroll
    for (int i = 0; i < 2; i++) {
        int f = tid + i * 256;   // 512 float4 per 64x32 tile
        rowi[i] = f >> 3;
        c4i[i]  = f & 7;
    }

    float4 xr[2], wr[2];
#pragma unroll
    for (int i = 0; i < 2; i++) {
        xr[i] = *(const float4*)(x  + (size_t)(m0 + rowi[i]) * D_DIM + c4i[i] * 4);
        wr[i] = *(const float4*)(wg + (size_t)rowi[i] * D_DIM + c4i[i] * 4);
    }

    uint64_t acc2[4][2];   // 4 tokens x (2 expert-pairs), packed f32x2
#pragma unroll
    for (int i = 0; i < 4; i++) { acc2[i][0] = 0ull; acc2[i][1] = 0ull; }

    const int NT = D_DIM / BK;
    for (int kt = 0; kt < NT; kt++) {
#pragma unroll
        for (int i = 0; i < 2; i++) {
            int c = c4i[i] * 4, r = rowi[i];
            Xs[c + 0][r] = xr[i].x; Xs[c + 1][r] = xr[i].y;
            Xs[c + 2][r] = xr[i].z; Xs[c + 3][r] = xr[i].w;
            Ws[c + 0][r] = wr[i].x; Ws[c + 1][r] = wr[i].y;
            Ws[c + 2][r] = wr[i].z; Ws[c + 3][r] = wr[i].w;
        }
        __syncthreads();

        if (kt + 1 < NT) {
            int k0 = (kt + 1) * BK;
#pragma unroll
            for (int i = 0; i < 2; i++) {
                xr[i] = *(const float4*)(x  + (size_t)(m0 + rowi[i]) * D_DIM + k0 + c4i[i] * 4);
                wr[i] = *(const float4*)(wg + (size_t)rowi[i] * D_DIM + k0 + c4i[i] * 4);
            }
        }

#pragma unroll
        for (int k = 0; k < BK; k++) {
            float4 a4 = *(const float4*)&Xs[k][ty * 4];
            float4 b4 = *(const float4*)&Ws[k][tx * 4];
            uint64_t bp0 = pack2(b4.x, b4.y);
            uint64_t bp1 = pack2(b4.z, b4.w);
            uint64_t a0  = pack2(a4.x, a4.x);
            uint64_t a1  = pack2(a4.y, a4.y);
            uint64_t a2  = pack2(a4.z, a4.z);
            uint64_t a3  = pack2(a4.w, a4.w);
            FMA2(acc2[0][0], a0, bp0); FMA2(acc2[0][1], a0, bp1);
            FMA2(acc2[1][0], a1, bp0); FMA2(acc2[1][1], a1, bp1);
            FMA2(acc2[2][0], a2, bp0); FMA2(acc2[2][1], a2, bp1);
            FMA2(acc2[3][0], a3, bp0); FMA2(acc2[3][1], a3, bp1);
        }
        __syncthreads();
    }

    // ---------- softmax epilogue ----------
#pragma unroll
    for (int i = 0; i < 4; i++) {
        float4 v;
        unpack2(acc2[i][0], v.x, v.y);
        unpack2(acc2[i][1], v.z, v.w);
        *(float4*)&Ls[ty * 4 + i][tx * 4] = v;
    }
    __syncthreads();

    const int wpid = tid >> 5, lane = tid & 31;
    float pa0 = 0.0f, pa1 = 0.0f;
#pragma unroll
    for (int t = 0; t < 8; t++) {
        const int row = wpid * 8 + t;
        float l0 = Ls[row][lane];
        float l1 = Ls[row][lane + 32];
        float mv; int mi;                     // argmax, first-occurrence tie-break
        if (l0 >= l1) { mv = l0; mi = lane; } else { mv = l1; mi = lane + 32; }
#pragma unroll
        for (int off = 16; off; off >>= 1) {
            float ov = __shfl_down_sync(0xffffffffu, mv, off);
            int   oi = __shfl_down_sync(0xffffffffu, mi, off);
            if (ov > mv || (ov == mv && oi < mi)) { mv = ov; mi = oi; }
        }
        mv = __shfl_sync(0xffffffffu, mv, 0);
        mi = __shfl_sync(0xffffffffu, mi, 0);

        float e0 = expf(l0 - mv), e1 = expf(l1 - mv);
        float sum = e0 + e1;
#pragma unroll
        for (int off = 16; off; off >>= 1) sum += __shfl_down_sync(0xffffffffu, sum, off);
        sum = __shfl_sync(0xffffffffu, sum, 0);
        float inv = 1.0f / sum;

        pa0 += e0 * inv;
        pa1 += e1 * inv;
        if (lane == 0) { g_idx[m0 + row] = mi; g_gate1[m0 + row] = inv; }
    }
    pg[wpid * E_EXP + lane]      = pa0;
    pg[wpid * E_EXP + lane + 32] = pa1;
    __syncthreads();
    if (tid < E_EXP) {
        float s = 0.0f;
#pragma unroll
        for (int w8 = 0; w8 < 8; w8++) s += pg[w8 * E_EXP + tid];
        g_partialGateSum[(size_t)blockIdx.x * E_EXP + tid] = s;
    }
}

// ---------------- scan + aux + scatter (single block; zeros already done) ----------------
__global__ void __launch_bounds__(1024) scan_scatter_kernel(float* __restrict__ combine,
                                                            float* __restrict__ maskp,
                                                            float* __restrict__ lauxp) {
    __shared__ int   hist[32 * E_EXP];
    __shared__ float red[16 * E_EXP];
    __shared__ int   cntS[E_EXP];
    __shared__ float vals[E_EXP];

    const int tid = threadIdx.x, lane = tid & 31, w = tid >> 5;
    hist[tid] = 0; hist[tid + 1024] = 0;
    __syncthreads();

    // phase 1: warp-local ordered ranks over 256 contiguous tokens
    int eArr[8], locArr[8];
    const int base = w * 256;
#pragma unroll
    for (int g = 0; g < 8; g++) {
        const int s = base + g * 32 + lane;
        const int e = g_idx[s];
        unsigned mask = __match_any_sync(0xffffffffu, e);
        int rank = __popc(mask & ((1u << lane) - 1u));
        int bcnt = hist[w * E_EXP + e];
        eArr[g] = e; locArr[g] = bcnt + rank;
        __syncwarp();
        if (lane == __ffs(mask) - 1) hist[w * E_EXP + e] = bcnt + __popc(mask);
        __syncwarp();
    }
    __syncthreads();

    // phase 2: exclusive prefix across warps, per expert
    if (tid < E_EXP) {
        int running = 0;
        for (int ww = 0; ww < 32; ww++) {
            int c = hist[ww * E_EXP + tid];
            hist[ww * E_EXP + tid] = running;
            running += c;
        }
        cntS[tid] = running;
    }
    __syncthreads();

    // phase 3: scatter combine + mask directly (capacity drop)
#pragma unroll
    for (int g = 0; g < 8; g++) {
        const int s   = base + g * 32 + lane;
        const int e   = eArr[g];
        const int loc = hist[w * E_EXP + e] + locArr[g];
        if (loc < CAP) {
            const size_t off = (size_t)s * (E_EXP * CAP) + (size_t)e * CAP + loc;
            const float gv = g_gate1[s];
            combine[off] = gv;
            if (maskp) maskp[off] = 1.0f;
        }
    }

    // phase 4: aux loss (deterministic fixed-order)
    {
        const int e = tid & 63, r = tid >> 6;  // 16 slices x 64 experts
        float sum = 0.0f;
        for (int p = r * 8; p < r * 8 + 8; p++) sum += g_partialGateSum[(size_t)p * E_EXP + e];
        red[(size_t)r * E_EXP + e] = sum;
    }
    __syncthreads();
    if (tid < E_EXP) {
        float me = 0.0f;
#pragma unroll
        for (int r = 0; r < 16; r++) me += red[r * E_EXP + tid];
        me /= (float)S_TOK;
        float ce = (float)cntS[tid] / (float)S_TOK;
        vals[tid] = me * ce;
    }
    __syncthreads();
    if (tid == 0 && lauxp) {
        float a = 0.0f;
        for (int e = 0; e < E_EXP; e++) a += vals[e];
        lauxp[0] = a * (float)E_EXP;   // mean * E*E == sum * E
    }
}

// ---------------- launch ----------------
extern "C" void kernel_launch(void* const* d_in, const int* in_sizes, int n_in,
                              void* d_out, int out_size) {
    const float* x  = (const float*)d_in[0];   // [S, D]
    const float* wg = (const float*)d_in[1];   // [E, D]
    float* out = (float*)d_out;

    const long long SEC = (long long)S_TOK * E_EXP * CAP;  // 67,108,864
    float* lauxp   = nullptr;
    float* combine = out;
    float* maskp   = nullptr;
    if ((long long)out_size >= 1 + 2 * SEC) {          // [l_aux, combine, mask]
        lauxp = out; combine = out + 1; maskp = out + 1 + SEC;
    } else if ((long long)out_size == 1 + SEC) {       // [l_aux, combine]
        lauxp = out; combine = out + 1;
    }

    fused_kernel<<<GEMM_BLOCKS + ZERO_BLOCKS, 256>>>(x, wg, out, (long long)out_size);
    scan_scatter_kernel<<<1, 1024>>>(combine, maskp, lauxp);
}